// round 17
// baseline (speedup 1.0000x reference)
#include <cuda_runtime.h>
#include <cuda_bf16.h>
#include <cstdint>

#define BATCH 64
#define SEQ   512
#define IDIM  300
#define HID   600
#define GATES 2400
#define NBLK  75
#define NTHR  256
#define NCH   15             // K chunks of 64: 5 x-chunks (300+bias+pad->320), 10 h-chunks (600+pad->640)
#define NSTG  5              // smem ring stages
// smem layout (bytes)
#define SM_W   1024                    // weight frags: per chunk 8KB (hi 4KB, lo 4KB)
#define SM_STG (SM_W + NCH*8192)       // 123904: 5 stages x 16KB A tiles (hi 8KB, lo 8KB)
#define SM_Z   (SM_STG + NSTG*16384)   // 205824: Zs 8448B + Zs2 8448B
#define SM_TOT (SM_Z + 2*8448)         // 222720

// ---------------- device scratch (static; no allocation) ----------------
__device__ uint32_t g_xA[(size_t)2*SEQ*5*4096];  // x tiles in A-fragment layout
__device__ uint32_t g_hA[2*2*10*4096];           // h tiles [dir][parity][chunk]
__device__ int g_bar[2*SEQ];

// ---------------- asm helpers ----------------
__device__ __forceinline__ void mbar_init(uint32_t a, uint32_t c) {
    asm volatile("mbarrier.init.shared.b64 [%0], %1;" :: "r"(a), "r"(c) : "memory");
}
__device__ __forceinline__ void mbar_expect(uint32_t a, uint32_t bytes) {
    asm volatile("mbarrier.arrive.expect_tx.shared.b64 _, [%0], %1;" :: "r"(a), "r"(bytes) : "memory");
}
__device__ __forceinline__ void bulk_g2s(uint32_t dst, const void* src, uint32_t bytes, uint32_t mb) {
    asm volatile("cp.async.bulk.shared::cluster.global.mbarrier::complete_tx::bytes [%0], [%1], %2, [%3];"
                 :: "r"(dst), "l"(src), "r"(bytes), "r"(mb) : "memory");
}
__device__ __forceinline__ void mbar_wait(uint32_t a, int ph) {
    asm volatile("{\n\t.reg .pred P;\n\tWL%=:\n\t"
        "mbarrier.try_wait.parity.acquire.cta.shared::cta.b64 P, [%0], %1, 0x989680;\n\t"
        "@P bra WD%=;\n\tbra WL%=;\n\tWD%=:\n\t}" :: "r"(a), "r"(ph) : "memory");
}
__device__ __forceinline__ void mma16816(float* d, const uint32_t* a, uint32_t b0, uint32_t b1) {
    asm volatile("mma.sync.aligned.m16n8k16.row.col.f32.bf16.bf16.f32 "
        "{%0,%1,%2,%3}, {%4,%5,%6,%7}, {%8,%9}, {%0,%1,%2,%3};"
        : "+f"(d[0]), "+f"(d[1]), "+f"(d[2]), "+f"(d[3])
        : "r"(a[0]), "r"(a[1]), "r"(a[2]), "r"(a[3]), "r"(b0), "r"(b1));
}
__device__ __forceinline__ float sigm(float x) { return 1.0f / (1.0f + __expf(-x)); }
__device__ __forceinline__ float tanh_s(float x) {
    float t = 1.0f - 2.0f / (__expf(2.0f * fabsf(x)) + 1.0f);
    return copysignf(t, x);
}
__device__ __forceinline__ uint32_t bf2_hi(float a, float b, float& ra, float& rb) {
    __nv_bfloat162 v; v.x = __float2bfloat16_rn(a); v.y = __float2bfloat16_rn(b);
    ra = a - __bfloat162float(v.x); rb = b - __bfloat162float(v.y);
    return *(uint32_t*)&v;
}
__device__ __forceinline__ uint32_t bf2(float a, float b) {
    __nv_bfloat162 v; v.x = __float2bfloat16_rn(a); v.y = __float2bfloat16_rn(b);
    return *(uint32_t*)&v;
}

// ---------------- reset ----------------
__global__ void brnn_reset() {
    int i = blockIdx.x*blockDim.x + threadIdx.x, st = gridDim.x*blockDim.x;
    for (int k = i; k < 2*2*10*4096; k += st) g_hA[k] = 0u;
    for (int k = i; k < 2*SEQ; k += st) g_bar[k] = 0;
}

// ---------------- x -> A-fragment-layout bf16 hi/lo tiles (backward gather, bias row) ----------------
__global__ void brnn_xprep(const float* __restrict__ x, const int* __restrict__ len) {
    const int t = blockIdx.x, dir = blockIdx.y, tid = threadIdx.x;
    __shared__ int L[BATCH];
    if (tid < BATCH) L[tid] = len[tid];
    __syncthreads();
    uint32_t* base = g_xA + ((size_t)(dir*SEQ + t)*5) * 4096;
    for (int slot = tid; slot < 5*2048; slot += NTHR) {
        int ch = slot >> 11, off = slot & 2047;
        int a = off & 3, lane = (off >> 2) & 31, mtg = off >> 7;
        int mt = mtg & 3, g = mtg >> 2;
        int lm = (a & 1)*8 + (lane >> 2);
        int m  = mt*16 + lm;
        int lk = ((a >> 1))*8 + (lane & 3)*2;
        int k  = ch*64 + g*16 + lk;
        int ts = t;
        if (dir) { int l = L[m]; if (t < l) ts = l - 1 - t; }
        const float* xs = x + ((size_t)m*SEQ + ts)*IDIM;
        float v0 = (k   < IDIM) ? xs[k]   : (k   == IDIM ? 1.0f : 0.0f);
        float v1 = (k+1 < IDIM) ? xs[k+1] : (k+1 == IDIM ? 1.0f : 0.0f);
        float r0, r1;
        uint32_t hi = bf2_hi(v0, v1, r0, r1);
        uint32_t lo = bf2(r0, r1);
        uint32_t* tb = base + (size_t)ch*4096;
        tb[off] = hi; tb[2048 + off] = lo;
    }
}

// ---------------- persistent bidirectional LSTM (bf16-split mma.sync) ----------------
__global__ void __launch_bounds__(NTHR, 1)
brnn_lstm(const float* __restrict__ Wf, const float* __restrict__ Uf, const float* __restrict__ bf,
          const float* __restrict__ Wb, const float* __restrict__ Ub, const float* __restrict__ bb,
          const int* __restrict__ lengths, float* __restrict__ out)
{
    const int dir = blockIdx.y, blk = blockIdx.x, tid = threadIdx.x;
    const int wid = tid >> 5, lane = tid & 31;
    const int mt = wid & 3, gh = wid >> 2;
    const int c0 = blk * 8;

    extern __shared__ __align__(1024) char sm[];
    const uint32_t smb = (uint32_t)__cvta_generic_to_shared(sm);
    const uint32_t bm = smb;                    // NSTG stage mbarriers @ 0,8,16,24,32
    float* Zs  = (float*)(sm + SM_Z);
    float* Zs2 = Zs + 2112;

    const float* W  = dir ? Wb : Wf;
    const float* U  = dir ? Ub : Uf;
    const float* bd = dir ? bb : bf;

    // ---- one-time: weights -> B-fragment layout bf16 hi/lo in smem ----
    for (int idx = tid; idx < NCH*1024; idx += NTHR) {
        int c = idx >> 10, rem = idx & 1023;
        int g = rem >> 8, rem2 = rem & 255;
        int ls = rem2 >> 3, r = rem2 & 7;
        int nt = r >> 1, kk = r & 1;
        int k0 = c*64 + g*16 + kk*8 + (ls & 3)*2;
        int n  = nt*8 + (ls >> 2);
        int gc = (n >> 3)*HID + c0 + (n & 7);
        float v0 = 0.f, v1 = 0.f;
        int k1 = k0 + 1;
        if (k0 < IDIM) v0 = W[(size_t)k0*GATES + gc];
        else if (k0 == IDIM) v0 = bd[gc];
        else if (k0 >= 320 && k0 < 920) v0 = U[(size_t)(k0-320)*GATES + gc];
        if (k1 < IDIM) v1 = W[(size_t)k1*GATES + gc];
        else if (k1 == IDIM) v1 = bd[gc];
        else if (k1 >= 320 && k1 < 920) v1 = U[(size_t)(k1-320)*GATES + gc];
        float r0, r1;
        uint32_t hi = bf2_hi(v0, v1, r0, r1);
        uint32_t lo = bf2(r0, r1);
        uint32_t boff = ((g*32 + ls)*8 + r)*4;
        *(uint32_t*)(sm + SM_W + c*8192 + boff)        = hi;
        *(uint32_t*)(sm + SM_W + c*8192 + 4096 + boff) = lo;
    }
    if (tid == 0) {
        #pragma unroll
        for (int i = 0; i < NSTG; i++) mbar_init(bm + i*8, 1);
    }
    __syncthreads();

    // gate-thread state: warp wid handles hidden j=wid for b=lane and b=lane+32
    const int bA = lane, bB = lane + 32;
    float crA = 0.f, crB = 0.f, acA = 0.f, acB = 0.f;
    const int LA = lengths[bA], LB = lengths[bB];
    // h-store fragment offsets (constant): element (m=b, k=320+8*blk+wid)
    const int ch_h = blk >> 3;
    const int gl   = (8*(blk & 7) + wid) >> 4;
    auto hoff = [&](int b) -> int {
        int lm = b & 15, mtb = b >> 4;
        int au = (lm >> 3) + 2*(blk & 1);
        int lp = (lm & 7)*4 + (wid >> 1);
        return ((gl*4 + mtb)*32 + lp)*4 + au;
    };
    const int offA = hoff(bA), offB = hoff(bB);
    const int hsel = wid & 1;

    int* bar = g_bar + dir*SEQ;
    int next_issue = 0;       // flat chunk counter (tid0 only)
    int fence_step = 0;       // last step whose h-read proxy fence was done

    for (int s = 0; s < SEQ; s++) {
        float acc[16];
        #pragma unroll
        for (int i = 0; i < 16; i++) acc[i] = 0.f;

        for (int c = 0; c < NCH; c++) {
            const int g = s*NCH + c;
            // ---- continuous producer: issue up to NSTG-1 chunks ahead, cross-step ----
            if (tid == 0) {
                while (next_issue < SEQ*NCH && next_issue <= g + (NSTG - 1)) {
                    const int ci = next_issue % NCH, si = next_issue / NCH;
                    if (ci >= 5 && si > 0) {
                        if (*(volatile int*)&bar[si-1] < NBLK) {
                            if (next_issue > g) break;          // defer ahead-issues
                            while (*(volatile int*)&bar[si-1] < NBLK) __nanosleep(32);
                        }
                        if (fence_step != si) {                 // once per step: order remote STGs
                            __threadfence();                    // before async-proxy bulk reads
                            asm volatile("fence.proxy.async;" ::: "memory");
                            fence_step = si;
                        }
                    }
                    const uint32_t* src = (ci < 5)
                        ? g_xA + ((size_t)(dir*SEQ + si)*5 + ci)*4096
                        : g_hA + ((size_t)(dir*2 + (si & 1))*10 + (ci - 5))*4096;
                    const int sti = next_issue % NSTG;
                    mbar_expect(bm + sti*8, 16384u);
                    bulk_g2s(smb + SM_STG + sti*16384, src, 16384u, bm + sti*8);
                    next_issue++;
                }
            }
            const int st = g % NSTG;
            mbar_wait(bm + st*8, (g / NSTG) & 1);

            const char* Ab = sm + SM_STG + st*16384;
            const char* Wc = sm + SM_W + c*8192;
            #pragma unroll
            for (int gi = 0; gi < 2; gi++) {
                const int gq = gh*2 + gi;
                const uint4 ah = *(const uint4*)(Ab + ((gq*4 + mt)*32 + lane)*16);
                const uint4 al = *(const uint4*)(Ab + 8192 + ((gq*4 + mt)*32 + lane)*16);
                const uint4 bh0 = *(const uint4*)(Wc + (gq*32 + lane)*32);
                const uint4 bh1 = *(const uint4*)(Wc + (gq*32 + lane)*32 + 16);
                const uint4 bl0 = *(const uint4*)(Wc + 4096 + (gq*32 + lane)*32);
                const uint4 bl1 = *(const uint4*)(Wc + 4096 + (gq*32 + lane)*32 + 16);
                const uint32_t* ahp = (const uint32_t*)&ah;
                const uint32_t* alp = (const uint32_t*)&al;
                mma16816(acc + 0,  ahp, bh0.x, bh0.y);
                mma16816(acc + 0,  ahp, bl0.x, bl0.y);
                mma16816(acc + 0,  alp, bh0.x, bh0.y);
                mma16816(acc + 4,  ahp, bh0.z, bh0.w);
                mma16816(acc + 4,  ahp, bl0.z, bl0.w);
                mma16816(acc + 4,  alp, bh0.z, bh0.w);
                mma16816(acc + 8,  ahp, bh1.x, bh1.y);
                mma16816(acc + 8,  ahp, bl1.x, bl1.y);
                mma16816(acc + 8,  alp, bh1.x, bh1.y);
                mma16816(acc + 12, ahp, bh1.z, bh1.w);
                mma16816(acc + 12, ahp, bl1.z, bl1.w);
                mma16816(acc + 12, alp, bh1.z, bh1.w);
            }
            __syncthreads();     // stage st fully consumed before producer re-arms it
        }

        // write partials: gh=0 -> Zs, gh=1 -> Zs2
        {
            float* Zt = gh ? Zs2 : Zs;
            #pragma unroll
            for (int nt = 0; nt < 4; nt++) {
                #pragma unroll
                for (int rr = 0; rr < 2; rr++) {
                    int b = mt*16 + (lane >> 2) + rr*8;
                    int n = nt*8 + 2*(lane & 3);
                    Zt[b*33 + n]     = acc[nt*4 + rr*2];
                    Zt[b*33 + n + 1] = acc[nt*4 + rr*2 + 1];
                }
            }
        }
        __syncthreads();

        // gates: warp wid = hidden j, lanes cover b and b+32 (bias already in GEMM)
        {
            uint32_t* tb = g_hA + ((size_t)(dir*2 + ((s + 1) & 1))*10 + ch_h)*4096;
            __nv_bfloat16* hp = (__nv_bfloat16*)tb;
            float zi = Zs[bA*33 + wid]      + Zs2[bA*33 + wid];
            float zf = Zs[bA*33 + 8 + wid]  + Zs2[bA*33 + 8 + wid];
            float zg = Zs[bA*33 + 16 + wid] + Zs2[bA*33 + 16 + wid];
            float zo = Zs[bA*33 + 24 + wid] + Zs2[bA*33 + 24 + wid];
            float cn = sigm(zf)*crA + sigm(zi)*tanh_s(zg);
            crA = cn;
            float h = sigm(zo)*tanh_s(cn);
            if (s < LA) acA += h;
            __nv_bfloat16 hh = __float2bfloat16_rn(h);
            __nv_bfloat16 hl = __float2bfloat16_rn(h - __bfloat162float(hh));
            hp[offA*2 + hsel] = hh;
            hp[4096 + offA*2 + hsel] = hl;

            zi = Zs[bB*33 + wid]      + Zs2[bB*33 + wid];
            zf = Zs[bB*33 + 8 + wid]  + Zs2[bB*33 + 8 + wid];
            zg = Zs[bB*33 + 16 + wid] + Zs2[bB*33 + 16 + wid];
            zo = Zs[bB*33 + 24 + wid] + Zs2[bB*33 + 24 + wid];
            cn = sigm(zf)*crB + sigm(zi)*tanh_s(zg);
            crB = cn;
            h = sigm(zo)*tanh_s(cn);
            if (s < LB) acB += h;
            hh = __float2bfloat16_rn(h);
            hl = __float2bfloat16_rn(h - __bfloat162float(hh));
            hp[offB*2 + hsel] = hh;
            hp[4096 + offB*2 + hsel] = hl;
        }
        __threadfence();
        __syncthreads();
        if (tid == 0) atomicAdd(&bar[s], 1);   // release step s
    }

    const float inv = 1.0f / (float)SEQ;
    out[bA*1200 + dir*HID + c0 + wid] = acA * inv;
    out[bB*1200 + dir*HID + c0 + wid] = acB * inv;
}

// ---------------- launch ----------------
extern "C" void kernel_launch(void* const* d_in, const int* in_sizes, int n_in,
                              void* d_out, int out_size) {
    (void)in_sizes; (void)out_size;
    const float* x   = (const float*)d_in[0];
    const int*   len = (const int*)d_in[1];
    int base = (n_in >= 9) ? 3 : 2;           // skip scalar 'training' if present
    const float* Wf = (const float*)d_in[base + 0];
    const float* Uf = (const float*)d_in[base + 1];
    const float* bf = (const float*)d_in[base + 2];
    const float* Wb = (const float*)d_in[base + 3];
    const float* Ub = (const float*)d_in[base + 4];
    const float* bb = (const float*)d_in[base + 5];
    float* out = (float*)d_out;

    cudaFuncSetAttribute(brnn_lstm, cudaFuncAttributeMaxDynamicSharedMemorySize, SM_TOT);

    brnn_reset<<<160, 256>>>();
    brnn_xprep<<<dim3(SEQ, 2), NTHR>>>(x, len);
    brnn_lstm<<<dim3(NBLK, 2), NTHR, SM_TOT>>>(Wf, Uf, bf, Wb, Ub, bb, len, out);
}